// round 2
// baseline (speedup 1.0000x reference)
#include <cuda_runtime.h>

// out[b,o,p] = sum_c refine_w[o,c] * x[b,c,p] + refine_b[o]
// (rest of the reference graph is dead code; x_back == x exactly)
// B=8, C=64, HW=65536, fp32.
//
// R2: packed fma.rn.f32x2 (FFMA2) + pre-duplicated f32x2 weights in shared
// ([c][o] layout, warp-broadcast LDS.128 pulls 2 weights/issue).

#define CC     64
#define HW     65536
#define BP     128          // pixels per block
#define NTHR   256          // 8 output-groups (warps) x 32 pixel-groups

typedef unsigned long long ull;

__device__ __forceinline__ void fma2(ull& d, ull a, ull b) {
    asm("fma.rn.f32x2 %0, %1, %2, %0;" : "+l"(d) : "l"(a), "l"(b));
}

__global__ __launch_bounds__(NTHR) void conv1x1_kernel(
    const float* __restrict__ x,
    const float* __restrict__ w,      // [64][64] (o,c)
    const float* __restrict__ bias,   // [64]
    float* __restrict__ out)
{
    __shared__ float sh_x[CC * BP];   // 32 KB  [c][p]
    __shared__ ull   sh_w2[CC * CC];  // 32 KB  [c][o] : (w,w) duplicated pairs

    const int t  = threadIdx.x;
    const int b  = blockIdx.y;
    const int p0 = blockIdx.x * BP;
    const size_t xbase = (size_t)b * CC * HW + p0;

    // ---- stage x tile: 64c x 128p = 2048 float4, coalesced ----
#pragma unroll
    for (int k = 0; k < 8; k++) {
        int i  = t + k * NTHR;        // [0, 2048)
        int c  = i >> 5;
        int f4 = i & 31;
        float4 v = *(const float4*)(x + xbase + (size_t)c * HW + f4 * 4);
        *(float4*)(sh_x + c * BP + f4 * 4) = v;
    }
    // ---- stage weights transposed + duplicated: sh_w2[c*64+o] = (w[o][c], w[o][c]) ----
#pragma unroll
    for (int k = 0; k < 16; k++) {
        int i = t + k * NTHR;         // i = c*64 + o
        int c = i >> 6;
        int o = i & 63;
        unsigned u = __float_as_uint(__ldg(w + o * CC + c));
        sh_w2[i] = (ull)u | ((ull)u << 32);
    }
    __syncthreads();

    const int r = t >> 5;   // warp id = output group: o in {4r..4r+3} U {32+4r..32+4r+3}
    const int j = t & 31;   // pixel group: p in {4j..4j+3}

    ull acc[8][2];
#pragma unroll
    for (int m = 0; m < 8; m++) { acc[m][0] = 0ull; acc[m][1] = 0ull; }

    const float* xp = sh_x + j * 4;
    const ull*   wA = sh_w2 + 4 * r;          // o = 4r, 4r+1
    const ull*   wC = sh_w2 + 32 + 4 * r;     // o = 32+4r, ...

#pragma unroll 8
    for (int c = 0; c < CC; c++) {
        // 4 pixels = 2 f32x2 lanes (warp-wide conflict-free LDS.128)
        ulonglong2 xv = *(const ulonglong2*)(xp + c * BP);
        // 8 duplicated weights in 4 broadcast LDS.128
        ulonglong2 w01 = *(const ulonglong2*)(wA + c * CC);       // o=4r,4r+1
        ulonglong2 w23 = *(const ulonglong2*)(wA + c * CC + 2);   // o=4r+2,4r+3
        ulonglong2 w45 = *(const ulonglong2*)(wC + c * CC);       // o=32+4r,+1
        ulonglong2 w67 = *(const ulonglong2*)(wC + c * CC + 2);   // o=32+4r+2,+3

        fma2(acc[0][0], w01.x, xv.x);  fma2(acc[0][1], w01.x, xv.y);
        fma2(acc[1][0], w01.y, xv.x);  fma2(acc[1][1], w01.y, xv.y);
        fma2(acc[2][0], w23.x, xv.x);  fma2(acc[2][1], w23.x, xv.y);
        fma2(acc[3][0], w23.y, xv.x);  fma2(acc[3][1], w23.y, xv.y);
        fma2(acc[4][0], w45.x, xv.x);  fma2(acc[4][1], w45.x, xv.y);
        fma2(acc[5][0], w45.y, xv.x);  fma2(acc[5][1], w45.y, xv.y);
        fma2(acc[6][0], w67.x, xv.x);  fma2(acc[6][1], w67.x, xv.y);
        fma2(acc[7][0], w67.y, xv.x);  fma2(acc[7][1], w67.y, xv.y);
    }

    // ---- epilogue: + bias, coalesced float4 stores ----
#pragma unroll
    for (int m = 0; m < 8; m++) {
        int o = (m < 4) ? (4 * r + m) : (32 + 4 * r + (m - 4));
        float bo = __ldg(bias + o);
        float2 lo = *(float2*)&acc[m][0];
        float2 hi = *(float2*)&acc[m][1];
        float4 v = make_float4(lo.x + bo, lo.y + bo, hi.x + bo, hi.y + bo);
        *(float4*)(out + ((size_t)b * CC + o) * HW + p0 + j * 4) = v;
    }
}

extern "C" void kernel_launch(void* const* d_in, const int* in_sizes, int n_in,
                              void* d_out, int out_size)
{
    (void)in_sizes; (void)n_in; (void)out_size;
    const float* x    = (const float*)d_in[0];   // x
    const float* w    = (const float*)d_in[11];  // refine_w
    const float* bias = (const float*)d_in[12];  // refine_b
    float* out = (float*)d_out;

    dim3 grid(HW / BP, 8);   // 512 pixel tiles x 8 batches
    conv1x1_kernel<<<grid, NTHR>>>(x, w, bias, out);
}

// round 6
// speedup vs baseline: 1.3080x; 1.3080x over previous
#include <cuda_runtime.h>

// out[b,o,p] = sum_c refine_w[o,c]*x[b,c,p] + refine_b[o]
// (rest of reference graph is dead: x_back == x exactly, _dead unused)
// B=8, C=64, HW=65536, fp32. FFMA-pipe-bound; maximize fma fraction of issues.

#define CC     64
#define HW     65536
#define BP     256          // pixels per block
#define NTHR   256          // 8 warps; warp r owns outputs 8r..8r+7, lanes x 8 pixels

__global__ __launch_bounds__(NTHR, 2) void conv1x1_kernel(
    const float* __restrict__ x,
    const float* __restrict__ w,      // [64][64] (o,c)
    const float* __restrict__ bias,   // [64]
    float* __restrict__ out)
{
    __shared__ float sh_x[CC * BP];   // 64 KB  [c][p]
    __shared__ float sh_w[CC * CC];   // 16 KB  [c][o]  (transposed!)

    const int t  = threadIdx.x;
    const int b  = blockIdx.y;
    const int p0 = blockIdx.x * BP;
    const size_t xbase = (size_t)b * CC * HW + p0;

    // ---- stage x tile: 64c x 256p = 4096 float4, fully coalesced ----
#pragma unroll
    for (int k = 0; k < 16; k++) {
        int i  = t + k * NTHR;        // [0, 4096)
        int c  = i >> 6;              // 64 float4 per channel row
        int f4 = i & 63;
        float4 v = *(const float4*)(x + xbase + (size_t)c * HW + f4 * 4);
        *(float4*)(sh_x + c * BP + f4 * 4) = v;
    }
    // ---- stage weights transposed: sh_w[c*64+o] = w[o*64+c] ----
    // gmem read strided (16KB, L2-resident), smem store contiguous.
#pragma unroll
    for (int k = 0; k < 16; k++) {
        int i = t + k * NTHR;         // i = c*64 + o
        int c = i >> 6;
        int o = i & 63;
        sh_w[i] = __ldg(w + o * CC + c);
    }
    __syncthreads();

    const int r = t >> 5;   // warp id: outputs 8r..8r+7
    const int j = t & 31;   // lane: pixels {4j..4j+3} and {128+4j..128+4j+3}

    const float* xp = sh_x + j * 4;
    const float* wp = sh_w + 8 * r;

    // acc[m][s]: m = output 0..7, s = pixel segment 0 (p=4j) / 1 (p=128+4j)
    float4 acc[8][2];
#pragma unroll
    for (int m = 0; m < 8; m++) {
        acc[m][0] = make_float4(0.f, 0.f, 0.f, 0.f);
        acc[m][1] = make_float4(0.f, 0.f, 0.f, 0.f);
    }

#define FMA4(A, S, V)                       \
    A.x = fmaf((S), (V).x, A.x);            \
    A.y = fmaf((S), (V).y, A.y);            \
    A.z = fmaf((S), (V).z, A.z);            \
    A.w = fmaf((S), (V).w, A.w);

#pragma unroll 8
    for (int c = 0; c < CC; c++) {
        // 2x LDS.128 x-pixels (conflict-free), 2x LDS.128 weights (broadcast)
        float4 xv0 = *(const float4*)(xp + c * BP);
        float4 xv1 = *(const float4*)(xp + c * BP + 128);
        float4 w03 = *(const float4*)(wp + c * CC);       // outs 8r..8r+3
        float4 w47 = *(const float4*)(wp + c * CC + 4);   // outs 8r+4..8r+7

        FMA4(acc[0][0], w03.x, xv0);  FMA4(acc[0][1], w03.x, xv1);
        FMA4(acc[1][0], w03.y, xv0);  FMA4(acc[1][1], w03.y, xv1);
        FMA4(acc[2][0], w03.z, xv0);  FMA4(acc[2][1], w03.z, xv1);
        FMA4(acc[3][0], w03.w, xv0);  FMA4(acc[3][1], w03.w, xv1);
        FMA4(acc[4][0], w47.x, xv0);  FMA4(acc[4][1], w47.x, xv1);
        FMA4(acc[5][0], w47.y, xv0);  FMA4(acc[5][1], w47.y, xv1);
        FMA4(acc[6][0], w47.z, xv0);  FMA4(acc[6][1], w47.z, xv1);
        FMA4(acc[7][0], w47.w, xv0);  FMA4(acc[7][1], w47.w, xv1);
    }

    // ---- epilogue: + bias, coalesced float4 stores (2 segs x 8 outs) ----
#pragma unroll
    for (int m = 0; m < 8; m++) {
        int o = 8 * r + m;
        float bo = __ldg(bias + o);
        float* op = out + ((size_t)b * CC + o) * HW + p0;
        float4 v0 = acc[m][0];
        v0.x += bo; v0.y += bo; v0.z += bo; v0.w += bo;
        *(float4*)(op + 4 * j) = v0;
        float4 v1 = acc[m][1];
        v1.x += bo; v1.y += bo; v1.z += bo; v1.w += bo;
        *(float4*)(op + 128 + 4 * j) = v1;
    }
}

extern "C" void kernel_launch(void* const* d_in, const int* in_sizes, int n_in,
                              void* d_out, int out_size)
{
    (void)in_sizes; (void)n_in; (void)out_size;
    const float* x    = (const float*)d_in[0];   // x
    const float* w    = (const float*)d_in[11];  // refine_w
    const float* bias = (const float*)d_in[12];  // refine_b
    float* out = (float*)d_out;

    dim3 grid(HW / BP, 8);   // 256 pixel tiles x 8 batches
    conv1x1_kernel<<<grid, NTHR>>>(x, w, bias, out);
}